// round 16
// baseline (speedup 1.0000x reference)
#include <cuda_runtime.h>
#include <cuda_bf16.h>
#include <math.h>
#include <stdint.h>

#define BB 4
#define SS 2048
#define DD 1024
#define HH 16
#define HDIM 64
#define MR (BB * SS)   // 8192

// ---- scratch (device globals: allocation-free per harness rules) ----
__device__ float g_base[(size_t)MR * 3 * DD];      // [8192,3072]
__device__ float g_hidden[(size_t)MR * DD];        // [8192,1024]
__device__ float g_ctrl[(size_t)MR * 80 + 16];     // [8192,80] (+pad)
__device__ float g_ys[(size_t)MR * DD];            // [8192,1024]
__device__ float g_mf[(size_t)BB * HH * HDIM * HDIM];

// ---- second stream + fork/join events (module-load construction; outside
// graph capture, no device allocation) ----
struct HxStreams {
    cudaStream_t s2;
    cudaEvent_t e1, e2;
    HxStreams() {
        cudaStreamCreateWithFlags(&s2, cudaStreamNonBlocking);
        cudaEventCreateWithFlags(&e1, cudaEventDisableTiming);
        cudaEventCreateWithFlags(&e2, cudaEventDisableTiming);
    }
};
static HxStreams g_hx;

// ===========================================================================
// helpers
// ===========================================================================
__device__ __forceinline__ void split2(float a0, float a1,
                                       unsigned& hi, unsigned& lo) {
    asm("cvt.rn.bf16x2.f32 %0, %1, %2;" : "=r"(hi) : "f"(a1), "f"(a0));
    float h0 = __uint_as_float(hi << 16);
    float h1 = __uint_as_float(hi & 0xffff0000u);
    float r0 = a0 - h0, r1 = a1 - h1;
    asm("cvt.rn.bf16x2.f32 %0, %1, %2;" : "=r"(lo) : "f"(r1), "f"(r0));
}

__device__ __forceinline__ void mma_bf16(float* c, const unsigned* a,
                                         unsigned b0, unsigned b1) {
    asm volatile(
        "mma.sync.aligned.m16n8k16.row.col.f32.bf16.bf16.f32 "
        "{%0,%1,%2,%3}, {%4,%5,%6,%7}, {%8,%9}, {%0,%1,%2,%3};"
        : "+f"(c[0]), "+f"(c[1]), "+f"(c[2]), "+f"(c[3])
        : "r"(a[0]), "r"(a[1]), "r"(a[2]), "r"(a[3]), "r"(b0), "r"(b1));
}

__device__ __forceinline__ void cpa16(uint32_t s, const void* g) {
    asm volatile("cp.async.ca.shared.global [%0], [%1], 16;"
                 :: "r"(s), "l"(g) : "memory");
}
__device__ __forceinline__ void cpa4(uint32_t s, const void* g) {
    asm volatile("cp.async.ca.shared.global [%0], [%1], 4;"
                 :: "r"(s), "l"(g) : "memory");
}
__device__ __forceinline__ void cpcommit() {
    asm volatile("cp.async.commit_group;" ::: "memory");
}
template <int N>
__device__ __forceinline__ void cpwait() {
    asm volatile("cp.async.wait_group %0;" :: "n"(N) : "memory");
}

// ===========================================================================
// Legacy bf16x3 GEMM (R5..R15-exact)
// ===========================================================================
#define TBM 128
#define TBK 16
#define XSTR 12
#define PLANE (TBM * XSTR)

__global__ __launch_bounds__(256) void gemm_bf16x3(
    const float* __restrict__ A, const float* __restrict__ B,
    const float* __restrict__ bias, float* __restrict__ C,
    int M, int N, int K, int act)
{
    __shared__ __align__(16) unsigned As[2][2 * PLANE];
    __shared__ __align__(16) unsigned Bs[2][2 * PLANE];

    int tid  = threadIdx.x;
    int lane = tid & 31;
    int warp = tid >> 5;
    int wm = warp >> 1, wn = warp & 1;
    int bm = blockIdx.y * TBM;
    int bn = blockIdx.x * 128;

    int arow = tid >> 1, ah = tid & 1;
    const float* Aptr = A + (size_t)(bm + arow) * K + ah * 8;
    int xa = (arow & 3) ^ ((arow >> 3) & 3);
    int ast_base = arow * XSTR + 4 * ah;
    int bnn = tid & 127, bh2 = tid >> 7;
    int gcol = bn + bnn;
    int xb = (bnn & 3) ^ ((bnn >> 3) & 3);
    int bst_base = bnn * XSTR + 4 * bh2;

    int fg = lane >> 2, ft = lane & 3;
    int idxA[2][2];
#pragma unroll
    for (int i = 0; i < 2; i++)
#pragma unroll
        for (int d = 0; d < 2; d++) {
            int row = wm * 32 + i * 16 + d * 8 + fg;
            idxA[i][d] = row * XSTR + (ft ^ (row & 3) ^ ((row >> 3) & 3));
        }
    int idxB[8];
#pragma unroll
    for (int j = 0; j < 8; j++) {
        int n = wn * 64 + j * 8 + fg;
        idxB[j] = n * XSTR + (ft ^ (n & 3) ^ ((n >> 3) & 3));
    }

    float acc[2][8][4];
#pragma unroll
    for (int i = 0; i < 2; i++)
#pragma unroll
        for (int j = 0; j < 8; j++)
#pragma unroll
            for (int l = 0; l < 4; l++) acc[i][j][l] = 0.f;

    {
        float4 f0 = *(const float4*)Aptr;
        float4 f1 = *(const float4*)(Aptr + 4);
        unsigned hi, lo;
        split2(f0.x, f0.y, hi, lo);
        As[0][ast_base + (0 ^ xa)] = hi; As[0][PLANE + ast_base + (0 ^ xa)] = lo;
        split2(f0.z, f0.w, hi, lo);
        As[0][ast_base + (1 ^ xa)] = hi; As[0][PLANE + ast_base + (1 ^ xa)] = lo;
        split2(f1.x, f1.y, hi, lo);
        As[0][ast_base + (2 ^ xa)] = hi; As[0][PLANE + ast_base + (2 ^ xa)] = lo;
        split2(f1.z, f1.w, hi, lo);
        As[0][ast_base + (3 ^ xa)] = hi; As[0][PLANE + ast_base + (3 ^ xa)] = lo;
#pragma unroll
        for (int i = 0; i < 4; i++) {
            int k = 8 * bh2 + 2 * i;
            float b0 = (gcol < N) ? B[(size_t)k * N + gcol] : 0.f;
            float b1 = (gcol < N) ? B[(size_t)(k + 1) * N + gcol] : 0.f;
            split2(b0, b1, hi, lo);
            Bs[0][bst_base + (i ^ xb)] = hi;
            Bs[0][PLANE + bst_base + (i ^ xb)] = lo;
        }
    }
    __syncthreads();

    int iters = K / TBK;
    for (int it = 1; it <= iters; it++) {
        bool has = (it < iters);
        float4 f0, f1;
        float bg[8];
        if (has) {
            int k0 = it * TBK;
            f0 = *(const float4*)(Aptr + k0);
            f1 = *(const float4*)(Aptr + k0 + 4);
#pragma unroll
            for (int i = 0; i < 4; i++) {
                int k = k0 + 8 * bh2 + 2 * i;
                bg[2 * i]     = (gcol < N) ? B[(size_t)k * N + gcol] : 0.f;
                bg[2 * i + 1] = (gcol < N) ? B[(size_t)(k + 1) * N + gcol] : 0.f;
            }
        }
        {
            const unsigned* Ab = As[(it - 1) & 1];
            const unsigned* Bb = Bs[(it - 1) & 1];
            unsigned ahf[2][4], alf[2][4];
#pragma unroll
            for (int i = 0; i < 2; i++) {
                ahf[i][0] = Ab[idxA[i][0]];
                ahf[i][1] = Ab[idxA[i][1]];
                ahf[i][2] = Ab[idxA[i][0] + 4];
                ahf[i][3] = Ab[idxA[i][1] + 4];
                alf[i][0] = Ab[PLANE + idxA[i][0]];
                alf[i][1] = Ab[PLANE + idxA[i][1]];
                alf[i][2] = Ab[PLANE + idxA[i][0] + 4];
                alf[i][3] = Ab[PLANE + idxA[i][1] + 4];
            }
#pragma unroll
            for (int j = 0; j < 8; j++) {
                unsigned bh0 = Bb[idxB[j]];
                unsigned bh1 = Bb[idxB[j] + 4];
                unsigned bl0 = Bb[PLANE + idxB[j]];
                unsigned bl1 = Bb[PLANE + idxB[j] + 4];
                mma_bf16(acc[0][j], ahf[0], bh0, bh1);
                mma_bf16(acc[1][j], ahf[1], bh0, bh1);
                mma_bf16(acc[0][j], ahf[0], bl0, bl1);
                mma_bf16(acc[1][j], ahf[1], bl0, bl1);
                mma_bf16(acc[0][j], alf[0], bh0, bh1);
                mma_bf16(acc[1][j], alf[1], bh0, bh1);
            }
        }
        if (has) {
            int buf = it & 1;
            unsigned hi, lo;
            split2(f0.x, f0.y, hi, lo);
            As[buf][ast_base + (0 ^ xa)] = hi; As[buf][PLANE + ast_base + (0 ^ xa)] = lo;
            split2(f0.z, f0.w, hi, lo);
            As[buf][ast_base + (1 ^ xa)] = hi; As[buf][PLANE + ast_base + (1 ^ xa)] = lo;
            split2(f1.x, f1.y, hi, lo);
            As[buf][ast_base + (2 ^ xa)] = hi; As[buf][PLANE + ast_base + (2 ^ xa)] = lo;
            split2(f1.z, f1.w, hi, lo);
            As[buf][ast_base + (3 ^ xa)] = hi; As[buf][PLANE + ast_base + (3 ^ xa)] = lo;
#pragma unroll
            for (int i = 0; i < 4; i++) {
                split2(bg[2 * i], bg[2 * i + 1], hi, lo);
                Bs[buf][bst_base + (i ^ xb)] = hi;
                Bs[buf][PLANE + bst_base + (i ^ xb)] = lo;
            }
        }
        __syncthreads();
    }

#pragma unroll
    for (int i = 0; i < 2; i++) {
        int row = bm + wm * 32 + i * 16 + fg;
#pragma unroll
        for (int j = 0; j < 8; j++) {
            int col = bn + wn * 64 + j * 8 + ft * 2;
            if (col < N) {
                float b0 = bias[col], b1 = bias[col + 1];
                float v0 = acc[i][j][0] + b0;
                float v1 = acc[i][j][1] + b1;
                float v2 = acc[i][j][2] + b0;
                float v3 = acc[i][j][3] + b1;
                if (act == 1) {
                    v0 = v0 / (1.f + __expf(-v0));
                    v1 = v1 / (1.f + __expf(-v1));
                    v2 = v2 / (1.f + __expf(-v2));
                    v3 = v3 / (1.f + __expf(-v3));
                }
                *(float2*)&C[(size_t)row * N + col] = make_float2(v0, v1);
                *(float2*)&C[(size_t)(row + 8) * N + col] = make_float2(v2, v3);
            }
        }
    }
}

// ===========================================================================
// Scan v8: chunked WY (T=16) with 8-way row split.
// 512 blocks = bh*8 + oct (8 rows each), 128 threads: rr=tid>>4, g=tid&15
// (4 cols each). Gram phase unchanged (full-row dots, threads 0..119).
// ===========================================================================
#define CT 16
#define KSTR 196

__global__ __launch_bounds__(128) void scan_kernel(
    const float* __restrict__ base,    // [B,S,H,3,HD]
    const float* __restrict__ ctrl,    // [B,S,H,5]
    const float* __restrict__ memory0, // [B,H,HD,HD]
    float* __restrict__ ys,            // [B,S,D]
    float* __restrict__ mfinal)        // [B,H,HD,HD]
{
    __shared__ __align__(16) float kqv[2][CT * KSTR];
    __shared__ float cbuf[2][CT * 8];
    __shared__ float sc0[CT], sc1[CT], sc2[CT], seta[CT];
    __shared__ float salpha[CT], sralpha[CT];
    __shared__ float gkk[CT * CT], gkq[CT * CT];

    int bh  = blockIdx.x >> 3;
    int oct = blockIdx.x & 7;
    int b = bh >> 4, h = bh & 15;
    int tid = threadIdx.x;
    int rr = tid >> 4;                 // 0..7
    int r  = oct * 8 + rr;             // global row 0..63
    int g  = tid & 15;                 // column group (4 cols)

    float m[4];
    {
        const float* M0 = memory0 + (((size_t)bh * HDIM + r) * HDIM + g * 4);
#pragma unroll
        for (int jj = 0; jj < 4; jj++) m[jj] = M0[jj];
    }

    const float* bsrc = base + ((size_t)b * SS * HH + h) * 192;  // +step*3072
    const float* csrc = ctrl + (size_t)b * SS * 80 + h * 5;      // +step*80
    float* yptr = ys + (size_t)b * SS * DD + h * HDIM + r;

    // Gram pair decode (once): thread t<120 -> pair (gj, gi), gj<gi
    int gj = 0, gi = 0;
    if (tid < 120) {
        int idx = tid, j = 0;
        while (idx >= 15 - j) { idx -= 15 - j; j++; }
        gj = j; gi = j + 1 + idx;
    }

    int lst = tid >> 3;   // step this thread loads (0..15)
    int lln = tid & 7;

#define CH_ISSUE(ck, bf) do {                                               \
        const float* bp_ = bsrc + (size_t)((ck) * CT + lst) * 3072;         \
        unsigned da_ = (unsigned)__cvta_generic_to_shared(                  \
                           &kqv[bf][lst * KSTR]);                           \
        _Pragma("unroll")                                                   \
        for (int i_ = 0; i_ < 6; i_++)                                      \
            cpa16(da_ + (unsigned)(lln + i_ * 8) * 16,                      \
                  bp_ + (lln + i_ * 8) * 4);                                \
        if (lln < 5)                                                        \
            cpa4((unsigned)__cvta_generic_to_shared(                        \
                     &cbuf[bf][lst * 8 + lln]),                             \
                 csrc + (size_t)((ck) * CT + lst) * 80 + lln);              \
        cpcommit();                                                         \
    } while (0)

    CH_ISSUE(0, 0);
    CH_ISSUE(1, 1);

    const int NCH = SS / CT;   // 128
    for (int c = 0; c < NCH; c++) {
        cpwait<1>();
        __syncthreads();       // chunk c data visible
        int buf = c & 1;
        const float* ch = kqv[buf];

        // per-step scalars
        if (tid < CT) {
            const float* cb = &cbuf[buf][tid * 8];
            sc0[tid] = cb[0]; sc1[tid] = cb[1]; sc2[tid] = cb[2];
            seta[tid] = 1.f / (1.f + __expf(-cb[3]));
            float ex = __expf(-cb[4]);
            float ra = 1.f + ex;           // 1/alpha
            sralpha[tid] = ra;
            salpha[tid] = 1.f / ra;        // alpha
        }

        // batched matvecs (parallel across i), 4-col slices
        float dk0[CT], dq0[CT];
#pragma unroll
        for (int i = 0; i < CT; i++) {
            const float* sp = ch + i * KSTR;
            float4 ka = *(const float4*)&sp[g * 4];
            float4 qa = *(const float4*)&sp[128 + g * 4];
            dk0[i] = m[0]*ka.x + m[1]*ka.y + m[2]*ka.z + m[3]*ka.w;
            dq0[i] = m[0]*qa.x + m[1]*qa.y + m[2]*qa.z + m[3]*qa.w;
        }
#pragma unroll
        for (int d = 1; d <= 8; d <<= 1) {
#pragma unroll
            for (int i = 0; i < CT; i++) {
                dk0[i] += __shfl_xor_sync(0xffffffffu, dk0[i], d);
                dq0[i] += __shfl_xor_sync(0xffffffffu, dq0[i], d);
            }
        }

        // Gram dots (2 per thread, threads 0..119; full 64-col rows)
        if (tid < 120) {
            const float* kj = ch + gj * KSTR;
            const float* ki = ch + gi * KSTR;
            float s1 = 0.f, s2 = 0.f;
#pragma unroll
            for (int cq = 0; cq < 16; cq++) {
                float4 a  = *(const float4*)&kj[cq * 4];
                float4 bq = *(const float4*)&ki[cq * 4];
                float4 qq = *(const float4*)&ki[128 + cq * 4];
                s1 += a.x*bq.x + a.y*bq.y + a.z*bq.z + a.w*bq.w;
                s2 += a.x*qq.x + a.y*qq.y + a.z*qq.z + a.w*qq.w;
            }
            gkk[gj * CT + gi] = s1;
            gkq[gj * CT + gi] = s2;
        }
        __syncthreads();       // scalars + Gram visible

        // forward substitution (short scalar chain; rank updates off-path)
        float f[CT];
        float Acur = 1.f, rAcur = 1.f;
#pragma unroll
        for (int i = 0; i < CT; i++) {
            float vv = ch[i * KSTR + 64 + r];
            float err = sc0[i] * Acur * dk0[i] - sc1[i] * vv;
            rAcur *= sralpha[i];
            Acur  *= salpha[i];
            float fi = seta[i] * sc0[i] * err * rAcur;
            f[i] = fi;
#pragma unroll
            for (int ii = i + 1; ii < CT; ii++) {
                dk0[ii] += fi * gkk[i * CT + ii];
                dq0[ii] += fi * gkq[i * CT + ii];
            }
        }
        float A16 = Acur;

        // y writes: step i written by column-group g == i (one writer/row)
        {
            float Ay = 1.f;
#pragma unroll
            for (int i = 0; i < CT; i++) {
                if (i == g)
                    yptr[(size_t)(c * CT + i) * DD] = sc2[i] * Ay * dq0[i];
                Ay *= salpha[i];
            }
        }

        // rank-16 update of M (4-col slices)
#pragma unroll
        for (int j = 0; j < CT; j++) {
            float4 ka = *(const float4*)&ch[j * KSTR + g * 4];
            float fj = f[j];
            m[0] += fj * ka.x; m[1] += fj * ka.y;
            m[2] += fj * ka.z; m[3] += fj * ka.w;
        }
#pragma unroll
        for (int jj = 0; jj < 4; jj++) m[jj] *= A16;

        __syncthreads();       // all reads of this buffer done
        if (c + 2 < NCH) CH_ISSUE(c + 2, buf);
        else cpcommit();
    }

    float* MF = mfinal + (((size_t)bh * HDIM + r) * HDIM + g * 4);
#pragma unroll
    for (int jj = 0; jj < 4; jj++) MF[jj] = m[jj];
}

// ===========================================================================
extern "C" void kernel_launch(void* const* d_in, const int* in_sizes, int n_in,
                              void* d_out, int out_size)
{
    (void)in_sizes; (void)n_in;
    const float* x       = (const float*)d_in[0];
    const float* memory0 = (const float*)d_in[1];
    const float* W_in    = (const float*)d_in[2];
    const float* b_in    = (const float*)d_in[3];
    const float* Wc1     = (const float*)d_in[4];
    const float* bc1     = (const float*)d_in[5];
    const float* Wc2     = (const float*)d_in[6];
    const float* bc2     = (const float*)d_in[7];
    const float* W_out   = (const float*)d_in[8];
    const float* b_out   = (const float*)d_in[9];

    float* out = (float*)d_out;

    float *base, *hidden, *ctrl, *ys, *mf_scratch;
    cudaGetSymbolAddress((void**)&base,       g_base);
    cudaGetSymbolAddress((void**)&hidden,     g_hidden);
    cudaGetSymbolAddress((void**)&ctrl,       g_ctrl);
    cudaGetSymbolAddress((void**)&ys,         g_ys);
    cudaGetSymbolAddress((void**)&mf_scratch, g_mf);

    const size_t OUT_ELEMS = (size_t)MR * DD;
    const size_t MF_ELEMS  = (size_t)BB * HH * HDIM * HDIM;
    float* mfinal = ((size_t)out_size >= OUT_ELEMS + MF_ELEMS)
                        ? (out + OUT_ELEMS) : mf_scratch;

    // ---- fork: ctrl path (gemm2 -> gemm3) on s2, base gemm on main ----
    cudaEventRecord(g_hx.e1, 0);
    cudaStreamWaitEvent(g_hx.s2, g_hx.e1, 0);

    gemm_bf16x3<<<dim3(DD / 128, MR / TBM), 256, 0, g_hx.s2>>>(
        x, Wc1, bc1, hidden, MR, DD, DD, 1);
    gemm_bf16x3<<<dim3(1, MR / TBM), 256, 0, g_hx.s2>>>(
        hidden, Wc2, bc2, ctrl, MR, 5 * HH, DD, 0);
    cudaEventRecord(g_hx.e2, g_hx.s2);

    gemm_bf16x3<<<dim3(3 * DD / 128, MR / TBM), 256>>>(
        x, W_in, b_in, base, MR, 3 * DD, DD, 0);

    // ---- join: scan needs base (main) + ctrl (s2) ----
    cudaStreamWaitEvent((cudaStream_t)0, g_hx.e2, 0);

    // chunked-WY scan (8-way row split)
    scan_kernel<<<BB * HH * 8, 128>>>(base, ctrl, memory0, ys, mfinal);
    // out = ys @ W_out + b_out
    gemm_bf16x3<<<dim3(DD / 128, MR / TBM), 256>>>(
        ys, W_out, b_out, out, MR, DD, DD, 0);
}

// round 17
// speedup vs baseline: 1.0241x; 1.0241x over previous
#include <cuda_runtime.h>
#include <cuda_bf16.h>
#include <math.h>
#include <stdint.h>

#define BB 4
#define SS 2048
#define DD 1024
#define HH 16
#define HDIM 64
#define MR (BB * SS)   // 8192

// ---- scratch (device globals: allocation-free per harness rules) ----
__device__ float g_base[(size_t)MR * 3 * DD];      // [8192,3072]
__device__ float g_hidden[(size_t)MR * DD];        // [8192,1024]
__device__ float g_ctrl[(size_t)MR * 80 + 16];     // [8192,80] (+pad)
__device__ float g_ys[(size_t)MR * DD];            // [8192,1024]
__device__ float g_mf[(size_t)BB * HH * HDIM * HDIM];

// ---- second stream + fork/join events (module-load construction; outside
// graph capture, no device allocation) ----
struct HxStreams {
    cudaStream_t s2;
    cudaEvent_t e1, e2;
    HxStreams() {
        cudaStreamCreateWithFlags(&s2, cudaStreamNonBlocking);
        cudaEventCreateWithFlags(&e1, cudaEventDisableTiming);
        cudaEventCreateWithFlags(&e2, cudaEventDisableTiming);
    }
};
static HxStreams g_hx;

// ===========================================================================
// helpers
// ===========================================================================
__device__ __forceinline__ void split2(float a0, float a1,
                                       unsigned& hi, unsigned& lo) {
    asm("cvt.rn.bf16x2.f32 %0, %1, %2;" : "=r"(hi) : "f"(a1), "f"(a0));
    float h0 = __uint_as_float(hi << 16);
    float h1 = __uint_as_float(hi & 0xffff0000u);
    float r0 = a0 - h0, r1 = a1 - h1;
    asm("cvt.rn.bf16x2.f32 %0, %1, %2;" : "=r"(lo) : "f"(r1), "f"(r0));
}

__device__ __forceinline__ void mma_bf16(float* c, const unsigned* a,
                                         unsigned b0, unsigned b1) {
    asm volatile(
        "mma.sync.aligned.m16n8k16.row.col.f32.bf16.bf16.f32 "
        "{%0,%1,%2,%3}, {%4,%5,%6,%7}, {%8,%9}, {%0,%1,%2,%3};"
        : "+f"(c[0]), "+f"(c[1]), "+f"(c[2]), "+f"(c[3])
        : "r"(a[0]), "r"(a[1]), "r"(a[2]), "r"(a[3]), "r"(b0), "r"(b1));
}

__device__ __forceinline__ void cpa16(uint32_t s, const void* g) {
    asm volatile("cp.async.ca.shared.global [%0], [%1], 16;"
                 :: "r"(s), "l"(g) : "memory");
}
__device__ __forceinline__ void cpa4(uint32_t s, const void* g) {
    asm volatile("cp.async.ca.shared.global [%0], [%1], 4;"
                 :: "r"(s), "l"(g) : "memory");
}
__device__ __forceinline__ void cpcommit() {
    asm volatile("cp.async.commit_group;" ::: "memory");
}
template <int N>
__device__ __forceinline__ void cpwait() {
    asm volatile("cp.async.wait_group %0;" :: "n"(N) : "memory");
}

// ===========================================================================
// Legacy bf16x3 GEMM (R5..R15-exact)
// ===========================================================================
#define TBM 128
#define TBK 16
#define XSTR 12
#define PLANE (TBM * XSTR)

__global__ __launch_bounds__(256) void gemm_bf16x3(
    const float* __restrict__ A, const float* __restrict__ B,
    const float* __restrict__ bias, float* __restrict__ C,
    int M, int N, int K, int act)
{
    __shared__ __align__(16) unsigned As[2][2 * PLANE];
    __shared__ __align__(16) unsigned Bs[2][2 * PLANE];

    int tid  = threadIdx.x;
    int lane = tid & 31;
    int warp = tid >> 5;
    int wm = warp >> 1, wn = warp & 1;
    int bm = blockIdx.y * TBM;
    int bn = blockIdx.x * 128;

    int arow = tid >> 1, ah = tid & 1;
    const float* Aptr = A + (size_t)(bm + arow) * K + ah * 8;
    int xa = (arow & 3) ^ ((arow >> 3) & 3);
    int ast_base = arow * XSTR + 4 * ah;
    int bnn = tid & 127, bh2 = tid >> 7;
    int gcol = bn + bnn;
    int xb = (bnn & 3) ^ ((bnn >> 3) & 3);
    int bst_base = bnn * XSTR + 4 * bh2;

    int fg = lane >> 2, ft = lane & 3;
    int idxA[2][2];
#pragma unroll
    for (int i = 0; i < 2; i++)
#pragma unroll
        for (int d = 0; d < 2; d++) {
            int row = wm * 32 + i * 16 + d * 8 + fg;
            idxA[i][d] = row * XSTR + (ft ^ (row & 3) ^ ((row >> 3) & 3));
        }
    int idxB[8];
#pragma unroll
    for (int j = 0; j < 8; j++) {
        int n = wn * 64 + j * 8 + fg;
        idxB[j] = n * XSTR + (ft ^ (n & 3) ^ ((n >> 3) & 3));
    }

    float acc[2][8][4];
#pragma unroll
    for (int i = 0; i < 2; i++)
#pragma unroll
        for (int j = 0; j < 8; j++)
#pragma unroll
            for (int l = 0; l < 4; l++) acc[i][j][l] = 0.f;

    {
        float4 f0 = *(const float4*)Aptr;
        float4 f1 = *(const float4*)(Aptr + 4);
        unsigned hi, lo;
        split2(f0.x, f0.y, hi, lo);
        As[0][ast_base + (0 ^ xa)] = hi; As[0][PLANE + ast_base + (0 ^ xa)] = lo;
        split2(f0.z, f0.w, hi, lo);
        As[0][ast_base + (1 ^ xa)] = hi; As[0][PLANE + ast_base + (1 ^ xa)] = lo;
        split2(f1.x, f1.y, hi, lo);
        As[0][ast_base + (2 ^ xa)] = hi; As[0][PLANE + ast_base + (2 ^ xa)] = lo;
        split2(f1.z, f1.w, hi, lo);
        As[0][ast_base + (3 ^ xa)] = hi; As[0][PLANE + ast_base + (3 ^ xa)] = lo;
#pragma unroll
        for (int i = 0; i < 4; i++) {
            int k = 8 * bh2 + 2 * i;
            float b0 = (gcol < N) ? B[(size_t)k * N + gcol] : 0.f;
            float b1 = (gcol < N) ? B[(size_t)(k + 1) * N + gcol] : 0.f;
            split2(b0, b1, hi, lo);
            Bs[0][bst_base + (i ^ xb)] = hi;
            Bs[0][PLANE + bst_base + (i ^ xb)] = lo;
        }
    }
    __syncthreads();

    int iters = K / TBK;
    for (int it = 1; it <= iters; it++) {
        bool has = (it < iters);
        float4 f0, f1;
        float bg[8];
        if (has) {
            int k0 = it * TBK;
            f0 = *(const float4*)(Aptr + k0);
            f1 = *(const float4*)(Aptr + k0 + 4);
#pragma unroll
            for (int i = 0; i < 4; i++) {
                int k = k0 + 8 * bh2 + 2 * i;
                bg[2 * i]     = (gcol < N) ? B[(size_t)k * N + gcol] : 0.f;
                bg[2 * i + 1] = (gcol < N) ? B[(size_t)(k + 1) * N + gcol] : 0.f;
            }
        }
        {
            const unsigned* Ab = As[(it - 1) & 1];
            const unsigned* Bb = Bs[(it - 1) & 1];
            unsigned ahf[2][4], alf[2][4];
#pragma unroll
            for (int i = 0; i < 2; i++) {
                ahf[i][0] = Ab[idxA[i][0]];
                ahf[i][1] = Ab[idxA[i][1]];
                ahf[i][2] = Ab[idxA[i][0] + 4];
                ahf[i][3] = Ab[idxA[i][1] + 4];
                alf[i][0] = Ab[PLANE + idxA[i][0]];
                alf[i][1] = Ab[PLANE + idxA[i][1]];
                alf[i][2] = Ab[PLANE + idxA[i][0] + 4];
                alf[i][3] = Ab[PLANE + idxA[i][1] + 4];
            }
#pragma unroll
            for (int j = 0; j < 8; j++) {
                unsigned bh0 = Bb[idxB[j]];
                unsigned bh1 = Bb[idxB[j] + 4];
                unsigned bl0 = Bb[PLANE + idxB[j]];
                unsigned bl1 = Bb[PLANE + idxB[j] + 4];
                mma_bf16(acc[0][j], ahf[0], bh0, bh1);
                mma_bf16(acc[1][j], ahf[1], bh0, bh1);
                mma_bf16(acc[0][j], ahf[0], bl0, bl1);
                mma_bf16(acc[1][j], ahf[1], bl0, bl1);
                mma_bf16(acc[0][j], alf[0], bh0, bh1);
                mma_bf16(acc[1][j], alf[1], bh0, bh1);
            }
        }
        if (has) {
            int buf = it & 1;
            unsigned hi, lo;
            split2(f0.x, f0.y, hi, lo);
            As[buf][ast_base + (0 ^ xa)] = hi; As[buf][PLANE + ast_base + (0 ^ xa)] = lo;
            split2(f0.z, f0.w, hi, lo);
            As[buf][ast_base + (1 ^ xa)] = hi; As[buf][PLANE + ast_base + (1 ^ xa)] = lo;
            split2(f1.x, f1.y, hi, lo);
            As[buf][ast_base + (2 ^ xa)] = hi; As[buf][PLANE + ast_base + (2 ^ xa)] = lo;
            split2(f1.z, f1.w, hi, lo);
            As[buf][ast_base + (3 ^ xa)] = hi; As[buf][PLANE + ast_base + (3 ^ xa)] = lo;
#pragma unroll
            for (int i = 0; i < 4; i++) {
                split2(bg[2 * i], bg[2 * i + 1], hi, lo);
                Bs[buf][bst_base + (i ^ xb)] = hi;
                Bs[buf][PLANE + bst_base + (i ^ xb)] = lo;
            }
        }
        __syncthreads();
    }

#pragma unroll
    for (int i = 0; i < 2; i++) {
        int row = bm + wm * 32 + i * 16 + fg;
#pragma unroll
        for (int j = 0; j < 8; j++) {
            int col = bn + wn * 64 + j * 8 + ft * 2;
            if (col < N) {
                float b0 = bias[col], b1 = bias[col + 1];
                float v0 = acc[i][j][0] + b0;
                float v1 = acc[i][j][1] + b1;
                float v2 = acc[i][j][2] + b0;
                float v3 = acc[i][j][3] + b1;
                if (act == 1) {
                    v0 = v0 / (1.f + __expf(-v0));
                    v1 = v1 / (1.f + __expf(-v1));
                    v2 = v2 / (1.f + __expf(-v2));
                    v3 = v3 / (1.f + __expf(-v3));
                }
                *(float2*)&C[(size_t)row * N + col] = make_float2(v0, v1);
                *(float2*)&C[(size_t)(row + 8) * N + col] = make_float2(v2, v3);
            }
        }
    }
}

// ===========================================================================
// Scan v9: chunked WY (T=16), 4-way row split, 256 THREADS per block.
// 256 blocks = bh*4 + quarter (16 rows each); threads: rr=tid>>4 (row 0..15),
// g=tid&15 (4 cols each). Gram: 120 pairs, 2 threads/pair (half-dots + one
// xor-1 shfl). Same total work as v7 (R15) with 2x warps/SM.
// ===========================================================================
#define CT 16
#define KSTR 196

__global__ __launch_bounds__(256) void scan_kernel(
    const float* __restrict__ base,    // [B,S,H,3,HD]
    const float* __restrict__ ctrl,    // [B,S,H,5]
    const float* __restrict__ memory0, // [B,H,HD,HD]
    float* __restrict__ ys,            // [B,S,D]
    float* __restrict__ mfinal)        // [B,H,HD,HD]
{
    __shared__ __align__(16) float kqv[2][CT * KSTR];
    __shared__ float cbuf[2][CT * 8];
    __shared__ float sc0[CT], sc1[CT], sc2[CT], seta[CT];
    __shared__ float salpha[CT], sralpha[CT];
    __shared__ float gkk[CT * CT], gkq[CT * CT];

    int bh      = blockIdx.x >> 2;
    int quarter = blockIdx.x & 3;
    int b = bh >> 4, h = bh & 15;
    int tid = threadIdx.x;
    int rr = tid >> 4;                 // 0..15
    int r  = quarter * 16 + rr;        // global row 0..63
    int g  = tid & 15;                 // column group (4 cols)

    float m[4];
    {
        const float* M0 = memory0 + (((size_t)bh * HDIM + r) * HDIM + g * 4);
#pragma unroll
        for (int jj = 0; jj < 4; jj++) m[jj] = M0[jj];
    }

    const float* bsrc = base + ((size_t)b * SS * HH + h) * 192;  // +step*3072
    const float* csrc = ctrl + (size_t)b * SS * 80 + h * 5;      // +step*80
    float* yptr = ys + (size_t)b * SS * DD + h * HDIM + r;

    // Gram pair decode: pair index pr = tid>>1 (clamped), half = tid&1
    int pr = tid >> 1;
    if (pr > 119) pr = 119;
    int half = tid & 1;
    int gj, gi;
    {
        int idx = pr, j = 0;
        while (idx >= 15 - j) { idx -= 15 - j; j++; }
        gj = j; gi = j + 1 + idx;
    }

    int lst = tid >> 4;   // step this thread loads (0..15)
    int lln = tid & 15;

#define CH_ISSUE(ck, bf) do {                                               \
        const float* bp_ = bsrc + (size_t)((ck) * CT + lst) * 3072;         \
        unsigned da_ = (unsigned)__cvta_generic_to_shared(                  \
                           &kqv[bf][lst * KSTR]);                           \
        _Pragma("unroll")                                                   \
        for (int i_ = 0; i_ < 3; i_++)                                      \
            cpa16(da_ + (unsigned)(lln + i_ * 16) * 16,                     \
                  bp_ + (lln + i_ * 16) * 4);                               \
        if (lln < 5)                                                        \
            cpa4((unsigned)__cvta_generic_to_shared(                        \
                     &cbuf[bf][lst * 8 + lln]),                             \
                 csrc + (size_t)((ck) * CT + lst) * 80 + lln);              \
        cpcommit();                                                         \
    } while (0)

    CH_ISSUE(0, 0);
    CH_ISSUE(1, 1);

    const int NCH = SS / CT;   // 128
    for (int c = 0; c < NCH; c++) {
        cpwait<1>();
        __syncthreads();       // chunk c data visible
        int buf = c & 1;
        const float* ch = kqv[buf];

        // per-step scalars
        if (tid < CT) {
            const float* cb = &cbuf[buf][tid * 8];
            sc0[tid] = cb[0]; sc1[tid] = cb[1]; sc2[tid] = cb[2];
            seta[tid] = 1.f / (1.f + __expf(-cb[3]));
            float ex = __expf(-cb[4]);
            float ra = 1.f + ex;           // 1/alpha
            sralpha[tid] = ra;
            salpha[tid] = 1.f / ra;        // alpha
        }

        // batched matvecs (parallel across i), 4-col slices
        float dk0[CT], dq0[CT];
#pragma unroll
        for (int i = 0; i < CT; i++) {
            const float* sp = ch + i * KSTR;
            float4 ka = *(const float4*)&sp[g * 4];
            float4 qa = *(const float4*)&sp[128 + g * 4];
            dk0[i] = m[0]*ka.x + m[1]*ka.y + m[2]*ka.z + m[3]*ka.w;
            dq0[i] = m[0]*qa.x + m[1]*qa.y + m[2]*qa.z + m[3]*qa.w;
        }
#pragma unroll
        for (int d = 1; d <= 8; d <<= 1) {
#pragma unroll
            for (int i = 0; i < CT; i++) {
                dk0[i] += __shfl_xor_sync(0xffffffffu, dk0[i], d);
                dq0[i] += __shfl_xor_sync(0xffffffffu, dq0[i], d);
            }
        }

        // Gram dots: 2 threads per pair, 32 elements each half
        {
            const float* kj = ch + gj * KSTR + half * 32;
            const float* ki = ch + gi * KSTR + half * 32;
            const float* qi = ch + gi * KSTR + 128 + half * 32;
            float s1 = 0.f, s2 = 0.f;
#pragma unroll
            for (int cq = 0; cq < 8; cq++) {
                float4 a  = *(const float4*)&kj[cq * 4];
                float4 bq = *(const float4*)&ki[cq * 4];
                float4 qq = *(const float4*)&qi[cq * 4];
                s1 += a.x*bq.x + a.y*bq.y + a.z*bq.z + a.w*bq.w;
                s2 += a.x*qq.x + a.y*qq.y + a.z*qq.z + a.w*qq.w;
            }
            s1 += __shfl_xor_sync(0xffffffffu, s1, 1);
            s2 += __shfl_xor_sync(0xffffffffu, s2, 1);
            if (tid < 240 && half == 0) {
                gkk[gj * CT + gi] = s1;
                gkq[gj * CT + gi] = s2;
            }
        }
        __syncthreads();       // scalars + Gram visible

        // forward substitution (short scalar chain; rank updates off-path)
        float f[CT];
        float Acur = 1.f, rAcur = 1.f;
#pragma unroll
        for (int i = 0; i < CT; i++) {
            float vv = ch[i * KSTR + 64 + r];
            float err = sc0[i] * Acur * dk0[i] - sc1[i] * vv;
            rAcur *= sralpha[i];
            Acur  *= salpha[i];
            float fi = seta[i] * sc0[i] * err * rAcur;
            f[i] = fi;
#pragma unroll
            for (int ii = i + 1; ii < CT; ii++) {
                dk0[ii] += fi * gkk[i * CT + ii];
                dq0[ii] += fi * gkq[i * CT + ii];
            }
        }
        float A16 = Acur;

        // y writes: step i written by column-group g == i (one writer/row)
        {
            float Ay = 1.f;
#pragma unroll
            for (int i = 0; i < CT; i++) {
                if (i == g)
                    yptr[(size_t)(c * CT + i) * DD] = sc2[i] * Ay * dq0[i];
                Ay *= salpha[i];
            }
        }

        // rank-16 update of M (4-col slices)
#pragma unroll
        for (int j = 0; j < CT; j++) {
            float4 ka = *(const float4*)&ch[j * KSTR + g * 4];
            float fj = f[j];
            m[0] += fj * ka.x; m[1] += fj * ka.y;
            m[2] += fj * ka.z; m[3] += fj * ka.w;
        }
#pragma unroll
        for (int jj = 0; jj < 4; jj++) m[jj] *= A16;

        __syncthreads();       // all reads of this buffer done
        if (c + 2 < NCH) CH_ISSUE(c + 2, buf);
        else cpcommit();
    }

    float* MF = mfinal + (((size_t)bh * HDIM + r) * HDIM + g * 4);
#pragma unroll
    for (int jj = 0; jj < 4; jj++) MF[jj] = m[jj];
}

// ===========================================================================
extern "C" void kernel_launch(void* const* d_in, const int* in_sizes, int n_in,
                              void* d_out, int out_size)
{
    (void)in_sizes; (void)n_in;
    const float* x       = (const float*)d_in[0];
    const float* memory0 = (const float*)d_in[1];
    const float* W_in    = (const float*)d_in[2];
    const float* b_in    = (const float*)d_in[3];
    const float* Wc1     = (const float*)d_in[4];
    const float* bc1     = (const float*)d_in[5];
    const float* Wc2     = (const float*)d_in[6];
    const float* bc2     = (const float*)d_in[7];
    const float* W_out   = (const float*)d_in[8];
    const float* b_out   = (const float*)d_in[9];

    float* out = (float*)d_out;

    float *base, *hidden, *ctrl, *ys, *mf_scratch;
    cudaGetSymbolAddress((void**)&base,       g_base);
    cudaGetSymbolAddress((void**)&hidden,     g_hidden);
    cudaGetSymbolAddress((void**)&ctrl,       g_ctrl);
    cudaGetSymbolAddress((void**)&ys,         g_ys);
    cudaGetSymbolAddress((void**)&mf_scratch, g_mf);

    const size_t OUT_ELEMS = (size_t)MR * DD;
    const size_t MF_ELEMS  = (size_t)BB * HH * HDIM * HDIM;
    float* mfinal = ((size_t)out_size >= OUT_ELEMS + MF_ELEMS)
                        ? (out + OUT_ELEMS) : mf_scratch;

    // ---- fork: ctrl path (gemm2 -> gemm3) on s2, base gemm on main ----
    cudaEventRecord(g_hx.e1, 0);
    cudaStreamWaitEvent(g_hx.s2, g_hx.e1, 0);

    gemm_bf16x3<<<dim3(DD / 128, MR / TBM), 256, 0, g_hx.s2>>>(
        x, Wc1, bc1, hidden, MR, DD, DD, 1);
    gemm_bf16x3<<<dim3(1, MR / TBM), 256, 0, g_hx.s2>>>(
        hidden, Wc2, bc2, ctrl, MR, 5 * HH, DD, 0);
    cudaEventRecord(g_hx.e2, g_hx.s2);

    gemm_bf16x3<<<dim3(3 * DD / 128, MR / TBM), 256>>>(
        x, W_in, b_in, base, MR, 3 * DD, DD, 0);

    // ---- join: scan needs base (main) + ctrl (s2) ----
    cudaStreamWaitEvent((cudaStream_t)0, g_hx.e2, 0);

    // chunked-WY scan (4-way row split, 256 threads)
    scan_kernel<<<BB * HH * 4, 256>>>(base, ctrl, memory0, ys, mfinal);
    // out = ys @ W_out + b_out
    gemm_bf16x3<<<dim3(DD / 128, MR / TBM), 256>>>(
        ys, W_out, b_out, out, MR, DD, DD, 0);
}